// round 17
// baseline (speedup 1.0000x reference)
#include <cuda_runtime.h>

#define GG    4096
#define MM    50
#define KK    30
#define HH    32
#define FIN   128
#define EPG   400      // edges per graph
#define DLAT  97
#define DDENSE 352
#define NN    (GG * MM)

typedef unsigned long long ull;

// ---- packed fp32x2 helpers (exact fp32) ----
__device__ __forceinline__ ull pack2(float a, float b) {
    ull r; asm("mov.b64 %0, {%1, %2};" : "=l"(r) : "f"(a), "f"(b)); return r;
}
__device__ __forceinline__ void fma2(ull& d, ull a, ull b) {
    asm("fma.rn.f32x2 %0, %1, %2, %0;" : "+l"(d) : "l"(a), "l"(b));
}
__device__ __forceinline__ float hsum2(ull v) {
    float lo, hi; asm("mov.b64 {%0, %1}, %2;" : "=f"(lo), "=f"(hi) : "l"(v));
    return lo + hi;
}
__device__ __forceinline__ ull d2u(double d) { return __double_as_longlong(d); }

// fast tanh via MUFU.EX2 + MUFU.RCP: rel err ~1e-6, correct +-1 saturation.
__device__ __forceinline__ float fast_tanh(float x) {
    float e = __expf(2.0f * x);
    return 1.0f - __fdividef(2.0f, e + 1.0f);
}

// static device scratch (no allocs allowed)
__device__ float  g_t0[(size_t)NN * HH];       // x @ W0
__device__ float  g_z[(size_t)GG * DDENSE];
__device__ float2 g_epack[(size_t)GG * EPG];   // (src_bits, norm), rows SORTED by src
__device__ int    g_rp[(size_t)GG * (MM + 1)];
__device__ float  g_snorm[(size_t)NN];         // dinv[n]^2

// ---------------------------------------------------------------------------
// Kernel P: per-graph GCN norm + CSR (grouped by dst, rows sorted -> fully
// deterministic accumulation order downstream). Persisted to global.
// ---------------------------------------------------------------------------
__global__ void __launch_bounds__(256)
prep_kernel(const int* __restrict__ ei, int E) {
    __shared__ int   cnt[MM], cnt2[MM], rp[MM + 1];
    __shared__ float dinv[MM];
    __shared__ int   es[EPG], ed[EPG];
    __shared__ __align__(16) float2 epk[EPG];   // float4-persisted: needs 16B align
    const int tid = threadIdx.x, lane = tid & 31, warp = tid >> 5;
    const int g = blockIdx.x;

    if (tid < MM) { cnt[tid] = 1; cnt2[tid] = 0; }   // self loop in cnt
    const int ebase = g * EPG;
    for (int e = tid; e < EPG; e += 256) {
        es[e] = ei[ebase + e] - g * MM;
        ed[e] = ei[E + ebase + e] - g * MM;
    }
    __syncthreads();

    for (int e = tid; e < EPG; e += 256) atomicAdd(&cnt[ed[e]], 1);
    __syncthreads();

    if (tid < MM) dinv[tid] = rsqrtf((float)cnt[tid]);
    if (warp == 0) {   // exclusive scan of (cnt-1)
        int a = (lane < MM) ? (cnt[lane] - 1) : 0;
        int b = (lane + 32 < MM) ? (cnt[lane + 32] - 1) : 0;
        int sa = a, sb = b;
#pragma unroll
        for (int o = 1; o < 32; o <<= 1) {
            int ta = __shfl_up_sync(0xffffffffu, sa, o);
            int tb = __shfl_up_sync(0xffffffffu, sb, o);
            if (lane >= o) { sa += ta; sb += tb; }
        }
        int tot_a = __shfl_sync(0xffffffffu, sa, 31);
        rp[lane] = sa - a;
        if (lane + 32 < MM) rp[lane + 32] = tot_a + sb - b;
        if (lane == 31) rp[MM] = tot_a + sb;
    }
    __syncthreads();

    // scatter (arbitrary order) then canonicalize each row by src sort.
    for (int e = tid; e < EPG; e += 256) {
        int d = ed[e], sl = es[e];
        int pos = rp[d] + atomicAdd(&cnt2[d], 1);
        epk[pos] = make_float2(__int_as_float(sl), dinv[sl] * dinv[d]);
    }
    __syncthreads();

    if (tid < MM) {
        int b = rp[tid], e1 = rp[tid + 1];
        for (int i = b + 1; i < e1; i++) {
            float2 key = epk[i];
            int ks = __float_as_int(key.x);
            int j = i - 1;
            while (j >= b && __float_as_int(epk[j].x) > ks) {
                epk[j + 1] = epk[j];
                j--;
            }
            epk[j + 1] = key;
        }
    }
    __syncthreads();

    // persist (coalesced)
    {
        const float4* src = reinterpret_cast<const float4*>(epk);
        float4* dst = reinterpret_cast<float4*>(&g_epack[(size_t)g * EPG]);
        for (int i = tid; i < EPG / 2; i += 256) dst[i] = src[i];
    }
    if (tid <= MM) g_rp[g * (MM + 1) + tid] = rp[tid];
    if (tid < MM)  g_snorm[(size_t)g * MM + tid] = dinv[tid] * dinv[tid];
}

// ---------------------------------------------------------------------------
// Kernel A: t0 = x @ W0 ([N,128] @ [128,32]). (measured 68 us, stable)
// ---------------------------------------------------------------------------
__global__ void __launch_bounds__(256)
xw0_kernel(const float* __restrict__ x, const float* __restrict__ W0,
           float* __restrict__ t0) {
    __shared__ __align__(16) float xs[64 * FIN];   // 32 KB
    const int tid = threadIdx.x, lane = tid & 31, warp = tid >> 5;
    const size_t base = (size_t)blockIdx.x * 64;

    {
        const float4* s = reinterpret_cast<const float4*>(x + base * FIN);
        float4* d = reinterpret_cast<float4*>(xs);
#pragma unroll
        for (int i = tid; i < 64 * FIN / 4; i += 256) d[i] = s[i];
    }
    __syncthreads();

    ull acc[8] = {0, 0, 0, 0, 0, 0, 0, 0};
    const float* xr = xs + warp * 8 * FIN;
#pragma unroll 4
    for (int k = 0; k < FIN; k += 4) {
        float wa = __ldg(&W0[(k + 0) * HH + lane]);
        float wb = __ldg(&W0[(k + 1) * HH + lane]);
        float wc = __ldg(&W0[(k + 2) * HH + lane]);
        float wd = __ldg(&W0[(k + 3) * HH + lane]);
        ull wab = pack2(wa, wb), wcd = pack2(wc, wd);
#pragma unroll
        for (int j = 0; j < 8; j++) {
            double2 v = *reinterpret_cast<const double2*>(&xr[j * FIN + k]);
            fma2(acc[j], d2u(v.x), wab);
            fma2(acc[j], d2u(v.y), wcd);
        }
    }
    float* o = t0 + (base + (size_t)warp * 8) * HH + lane;
#pragma unroll
    for (int j = 0; j < 8; j++) o[j * HH] = hsum2(acc[j]);
}

// ---------------------------------------------------------------------------
// Kernel B: per-graph GCN agg1 + layers 2-4 + sort-pool + conv1/conv2.
// CSR preamble eliminated (prep kernel); ~37KB smem.
// ---------------------------------------------------------------------------
struct Smem {
    alignas(16) float  h[MM * HH];     // 6400
    alignas(16) float  tmp[MM * HH];   // 6400
    alignas(16) float2 epack[EPG];     // 3200
    float  lat[MM * DLAT];             // 19400
    float  pooled[16 * 15];            // 960
    float  snorm[MM];
    float  h4v[MM];
    int    rp[MM + 1];
    int    sel[KK];
};

// h[M,32](smem) @ W[32,32](global, L1-hot) -> tmp[M,32]. f32x2 k-pairs.
__device__ __forceinline__ void gcn_matmul32(const float* __restrict__ in,
                                             const float* __restrict__ Wg,
                                             float* __restrict__ tmp,
                                             int warp, int lane) {
    int nbase = warp * 7;
    if (nbase >= MM) return;
    int ncnt = MM - nbase; if (ncnt > 7) ncnt = 7;
    ull acc[7] = {0, 0, 0, 0, 0, 0, 0};
#pragma unroll
    for (int k = 0; k < HH; k += 4) {
        float wa = __ldg(&Wg[(k + 0) * HH + lane]);
        float wb = __ldg(&Wg[(k + 1) * HH + lane]);
        float wc = __ldg(&Wg[(k + 2) * HH + lane]);
        float wd = __ldg(&Wg[(k + 3) * HH + lane]);
        ull wab = pack2(wa, wb), wcd = pack2(wc, wd);
#pragma unroll
        for (int j = 0; j < 7; j++) {
            if (j < ncnt) {
                double2 v = *reinterpret_cast<const double2*>(&in[(nbase + j) * HH + k]);
                fma2(acc[j], d2u(v.x), wab);
                fma2(acc[j], d2u(v.y), wcd);
            }
        }
    }
    for (int j = 0; j < ncnt; j++) tmp[(nbase + j) * HH + lane] = hsum2(acc[j]);
}

// gather-aggregate + self loop + bias + tanh -> h and lat column block.
// Four nodes (i, i+13, i+26, i+39) per iteration: 4-way ILP on LDS->FMA chains.
__device__ __forceinline__ void gcn_agg(Smem& s, int coloff, float bias,
                                        int warp, int lane) {
    for (int i = warp; i < 13; i += 8) {
        int n0 = i, n1 = i + 13, n2 = i + 26, n3 = i + 39;
        bool v3 = n3 < MM;
        float a0 = s.tmp[n0 * HH + lane] * s.snorm[n0];
        float a1 = s.tmp[n1 * HH + lane] * s.snorm[n1];
        float a2 = s.tmp[n2 * HH + lane] * s.snorm[n2];
        float a3 = v3 ? s.tmp[n3 * HH + lane] * s.snorm[n3] : 0.f;
        int e0 = s.rp[n0], c0 = s.rp[n0 + 1] - e0;
        int e1 = s.rp[n1], c1 = s.rp[n1 + 1] - e1;
        int e2 = s.rp[n2], c2 = s.rp[n2 + 1] - e2;
        int e3 = v3 ? s.rp[n3] : 0, c3 = v3 ? s.rp[n3 + 1] - e3 : 0;
        int m = max(max(c0, c1), max(c2, c3));
        for (int k = 0; k < m; k++) {
            if (k < c0) {
                float2 p = s.epack[e0 + k];
                a0 = fmaf(s.tmp[__float_as_int(p.x) * HH + lane], p.y, a0);
            }
            if (k < c1) {
                float2 p = s.epack[e1 + k];
                a1 = fmaf(s.tmp[__float_as_int(p.x) * HH + lane], p.y, a1);
            }
            if (k < c2) {
                float2 p = s.epack[e2 + k];
                a2 = fmaf(s.tmp[__float_as_int(p.x) * HH + lane], p.y, a2);
            }
            if (k < c3) {
                float2 p = s.epack[e3 + k];
                a3 = fmaf(s.tmp[__float_as_int(p.x) * HH + lane], p.y, a3);
            }
        }
        float r0 = fast_tanh(a0 + bias);
        float r1 = fast_tanh(a1 + bias);
        float r2 = fast_tanh(a2 + bias);
        s.lat[n0 * DLAT + coloff + lane] = r0;
        s.h[n0 * HH + lane] = r0;
        s.lat[n1 * DLAT + coloff + lane] = r1;
        s.h[n1 * HH + lane] = r1;
        s.lat[n2 * DLAT + coloff + lane] = r2;
        s.h[n2 * HH + lane] = r2;
        if (v3) {
            float r3 = fast_tanh(a3 + bias);
            s.lat[n3 * DLAT + coloff + lane] = r3;
            s.h[n3 * HH + lane] = r3;
        }
    }
}

__global__ void __launch_bounds__(256, 5)
graph_kernel(const float* __restrict__ t0,
             const float* __restrict__ b0,
             const float* __restrict__ W1, const float* __restrict__ b1,
             const float* __restrict__ W2, const float* __restrict__ b2,
             const float* __restrict__ W3, const float* __restrict__ b3,
             const float* __restrict__ C1w, const float* __restrict__ C1b,
             const float* __restrict__ C2w, const float* __restrict__ C2b) {
    extern __shared__ __align__(16) char raw[];
    Smem& s = *reinterpret_cast<Smem*>(raw);
    const int tid = threadIdx.x, lane = tid & 31, warp = tid >> 5;
    const int g = blockIdx.x;

    // ---- stage t0 slice + prebuilt CSR (all coalesced) ----
    {
        const float4* tsrc = reinterpret_cast<const float4*>(t0 + (size_t)g * MM * HH);
        float4* tdst = reinterpret_cast<float4*>(s.tmp);
        for (int i = tid; i < MM * HH / 4; i += 256) tdst[i] = tsrc[i];

        const float4* esrc = reinterpret_cast<const float4*>(&g_epack[(size_t)g * EPG]);
        float4* edst = reinterpret_cast<float4*>(s.epack);
        for (int i = tid; i < EPG / 2; i += 256) edst[i] = esrc[i];
    }
    if (tid <= MM) s.rp[tid] = __ldg(&g_rp[g * (MM + 1) + tid]);
    if (tid >= 64 && tid < 64 + MM) s.snorm[tid - 64] = __ldg(&g_snorm[(size_t)g * MM + tid - 64]);
    __syncthreads();

    // ---- layer 1 aggregation (t0 already = x@W0) ----
    gcn_agg(s, 0, __ldg(&b0[lane]), warp, lane);
    __syncthreads();

    // ---- layers 2-3 ----
    gcn_matmul32(s.h, W1, s.tmp, warp, lane);
    __syncthreads();
    gcn_agg(s, 32, __ldg(&b1[lane]), warp, lane);
    __syncthreads();

    gcn_matmul32(s.h, W2, s.tmp, warp, lane);
    __syncthreads();
    gcn_agg(s, 64, __ldg(&b2[lane]), warp, lane);
    __syncthreads();

    // ---- layer 4: H=32 -> 1 ----
    {
        float w3 = __ldg(&W3[lane]);
        for (int n = warp; n < MM; n += 8) {
            float v = s.h[n * HH + lane] * w3;
#pragma unroll
            for (int o = 16; o; o >>= 1) v += __shfl_xor_sync(0xffffffffu, v, o);
            if (lane == 0) s.tmp[n] = v;
        }
    }
    __syncthreads();
    if (tid < MM) {
        int n = tid;
        float a = s.tmp[n] * s.snorm[n];
        int e1 = s.rp[n + 1];
        for (int e = s.rp[n]; e < e1; e++) {
            float2 p = s.epack[e];
            a = fmaf(s.tmp[__float_as_int(p.x)], p.y, a);
        }
        float r = fast_tanh(a + __ldg(&b3[0]));
        s.lat[n * DLAT + 96] = r;
        s.h4v[n] = r;
    }
    __syncthreads();

    // ---- sort-pool: exact rank == stable argsort(-h4) ----
    if (tid < MM) {
        float vi = s.h4v[tid];
        int r = 0;
        for (int j = 0; j < MM; j++) {
            float vj = s.h4v[j];
            r += (vj > vi) || (vj == vi && j < tid);
        }
        if (r < KK) s.sel[r] = tid;
    }
    __syncthreads();

    // ---- conv1: warp = 2 channels x 30 slots; maxpool fused via shfl ----
    {
        int c0 = warp * 2;
        float a0 = 0.f, a1 = 0.f;
        if (lane < KK) {
            const float* lr = &s.lat[s.sel[lane] * DLAT];
            const float* cw0 = &C1w[c0 * DLAT];
            const float* cw1 = &C1w[(c0 + 1) * DLAT];
            a0 = __ldg(&C1b[c0]);
            a1 = __ldg(&C1b[c0 + 1]);
#pragma unroll 4
            for (int d = 0; d < DLAT; d++) {
                float v = lr[d];
                a0 = fmaf(v, __ldg(&cw0[d]), a0);
                a1 = fmaf(v, __ldg(&cw1[d]), a1);
            }
            a0 = fmaxf(a0, 0.f);
            a1 = fmaxf(a1, 0.f);
        }
        float p0 = __shfl_down_sync(0xffffffffu, a0, 1);
        float p1 = __shfl_down_sync(0xffffffffu, a1, 1);
        if (lane < KK && !(lane & 1)) {
            int u = lane >> 1;
            s.pooled[c0 * 15 + u] = fmaxf(a0, p0);
            s.pooled[(c0 + 1) * 15 + u] = fmaxf(a1, p1);
        }
    }
    __syncthreads();

    // ---- conv2 (16->32, k=5) + relu -> global scratch ----
    for (int o2 = tid; o2 < DDENSE; o2 += 256) {
        int o = o2 / 11, u = o2 % 11;
        float a = __ldg(&C2b[o]);
#pragma unroll
        for (int i = 0; i < 16; i++) {
            const float* pw = &C2w[(o * 16 + i) * 5];
            const float* pp = &s.pooled[i * 15 + u];
#pragma unroll
            for (int k2 = 0; k2 < 5; k2++) a = fmaf(pp[k2], __ldg(&pw[k2]), a);
        }
        g_z[(size_t)g * DDENSE + o2] = fmaxf(a, 0.f);
    }
}

// ---------------------------------------------------------------------------
// Kernel C: fused dense. 8 graphs / CTA, 128 threads (unchanged).
// ---------------------------------------------------------------------------
__global__ void __launch_bounds__(128)
dense_kernel(const float* __restrict__ L1w, const float* __restrict__ L1b,
             const float* __restrict__ L2w, const float* __restrict__ L2b,
             float* __restrict__ out) {
    __shared__ __align__(16) float zs[8][DDENSE];
    __shared__ float red[4][8];
    const int tid = threadIdx.x, lane = tid & 31, warp = tid >> 5;
    const int gbase = blockIdx.x * 8;

    {
        const float4* zsrc = reinterpret_cast<const float4*>(&g_z[(size_t)gbase * DDENSE]);
        float4* zdst = reinterpret_cast<float4*>(&zs[0][0]);
        for (int i = tid; i < 8 * DDENSE / 4; i += 128) zdst[i] = zsrc[i];
    }
    __syncthreads();

    const int ch = warp * 32 + lane;
    float acc[8];
    float l1b = __ldg(&L1b[ch]);
#pragma unroll
    for (int j = 0; j < 8; j++) acc[j] = l1b;

#pragma unroll 2
    for (int d = 0; d < DDENSE; d += 4) {
        float w0 = __ldg(&L1w[(d + 0) * 128 + ch]);
        float w1 = __ldg(&L1w[(d + 1) * 128 + ch]);
        float w2 = __ldg(&L1w[(d + 2) * 128 + ch]);
        float w3 = __ldg(&L1w[(d + 3) * 128 + ch]);
#pragma unroll
        for (int j = 0; j < 8; j++) {
            float4 zv = *reinterpret_cast<const float4*>(&zs[j][d]);
            acc[j] = fmaf(zv.x, w0, fmaf(zv.y, w1, fmaf(zv.z, w2, fmaf(zv.w, w3, acc[j]))));
        }
    }

    float w2v = __ldg(&L2w[ch]);
#pragma unroll
    for (int j = 0; j < 8; j++) {
        float p = fmaxf(acc[j], 0.f) * w2v;
#pragma unroll
        for (int o = 16; o; o >>= 1) p += __shfl_xor_sync(0xffffffffu, p, o);
        if (lane == 0) red[warp][j] = p;
    }
    __syncthreads();

    if (tid < 8) {
        out[gbase + tid] = red[0][tid] + red[1][tid] + red[2][tid] + red[3][tid]
                         + __ldg(&L2b[0]);
    }
}

extern "C" void kernel_launch(void* const* d_in, const int* in_sizes, int n_in,
                              void* d_out, int out_size) {
    const float* x   = (const float*)d_in[0];
    const int*   ei  = (const int*)d_in[1];
    // d_in[2] = batch (unused; graphs are contiguous equal-size blocks)
    const float* W0  = (const float*)d_in[3];
    const float* b0  = (const float*)d_in[4];
    const float* W1  = (const float*)d_in[5];
    const float* b1  = (const float*)d_in[6];
    const float* W2  = (const float*)d_in[7];
    const float* b2  = (const float*)d_in[8];
    const float* W3  = (const float*)d_in[9];
    const float* b3  = (const float*)d_in[10];
    const float* C1w = (const float*)d_in[11];
    const float* C1b = (const float*)d_in[12];
    const float* C2w = (const float*)d_in[13];
    const float* C2b = (const float*)d_in[14];
    const float* L1w = (const float*)d_in[15];
    const float* L1b = (const float*)d_in[16];
    const float* L2w = (const float*)d_in[17];
    const float* L2b = (const float*)d_in[18];

    const int E = in_sizes[1] / 2;

    float* t0;
    cudaGetSymbolAddress((void**)&t0, g_t0);

    const int smem = (int)sizeof(Smem);
    cudaFuncSetAttribute(graph_kernel, cudaFuncAttributeMaxDynamicSharedMemorySize, smem);

    prep_kernel<<<GG, 256>>>(ei, E);
    xw0_kernel<<<NN / 64, 256>>>(x, W0, t0);
    graph_kernel<<<GG, 256, smem>>>(t0, b0, W1, b1, W2, b2, W3, b3,
                                    C1w, C1b, C2w, C2b);
    dense_kernel<<<GG / 8, 128>>>(L1w, L1b, L2w, L2b, (float*)d_out);
}